// round 8
// baseline (speedup 1.0000x reference)
#include <cuda_runtime.h>
#include <math_constants.h>
#include <cstdint>

// Problem constants
#define BB   8
#define CC   256
#define CR   128
#define TT   16
#define HWD  784            // 28*28
#define THW  12544          // 16*784
#define KTOP 196            // 784/4
#define NROW 1024           // B*CR
#define BN_EPS 1e-5f

// Scratch buffers
__device__ float g_Q [BB * CR * THW];
__device__ float g_K [BB * CR * THW];
__device__ float g_V [BB * CR * THW];
__device__ float g_Qt[NROW * TT * KTOP];
__device__ float g_Kt[NROW * TT * KTOP];
__device__ float g_Y [BB * CR * THW];

__device__ __forceinline__ uint32_t f2tf32(float x) {
    uint32_t u;
    asm("cvt.rna.tf32.f32 %0, %1;" : "=r"(u) : "f"(x));
    return u;
}
__device__ __forceinline__ void cpasync16(uint32_t daddr, const void* src) {
    asm volatile("cp.async.ca.shared.global [%0], [%1], 16;\n"
                 :: "r"(daddr), "l"(src));
}

// ---------------------------------------------------------------------------
// Pipelined tf32 tensor-core GEMM, 2-stage cp.async double buffering.
// __launch_bounds__(256, 2): cap regs at 128 -> 2 CTAs/SM (16 warps) for
// latency hiding (R7 profile: 133 regs -> 1 CTA/SM, issue 24%).
// ---------------------------------------------------------------------------
#define TBM 128
#define TBN 128
#define TBK 16
#define APAD 20
#define BPAD 136

__global__ __launch_bounds__(256, 2) void gemm_tf32_pipe_kernel(
    const float* __restrict__ A0, const float* __restrict__ A1,
    const float* __restrict__ A2,
    const float* __restrict__ Bmat,
    float* __restrict__ C0, float* __restrict__ C1, float* __restrict__ C2,
    const float* __restrict__ bias0, const float* __restrict__ bias1,
    const float* __restrict__ bias2,
    const float* __restrict__ gamma,
    const float* __restrict__ beta,
    const float* __restrict__ bn_mean,
    const float* __restrict__ bn_var,
    const float* __restrict__ xres,
    int M, int K, int mode)
{
    const int b    = blockIdx.z;
    const int bx   = blockIdx.x;
    const int n0   = blockIdx.y * TBN;
    const int tid  = threadIdx.x;
    const int lane = tid & 31;
    const int wid  = tid >> 5;
    const int wm   = wid >> 1;
    const int wn   = wid & 1;

    const float* A;
    const float* bias;
    float* C;
    int m0;
    if (mode == 0) {
        A    = (bx == 0) ? A0 : (bx == 1) ? A1 : A2;
        bias = (bx == 0) ? bias0 : (bx == 1) ? bias1 : bias2;
        C    = (bx == 0) ? C0 : (bx == 1) ? C1 : C2;
        m0   = 0;
    } else {
        A = A0; bias = bias0; C = C0;
        m0 = bx * TBM;
    }

    const float* Bb = Bmat + (size_t)b * K * THW;
    float*       Cb = C    + (size_t)b * M * THW;

    __shared__ float As[2][TBM][APAD];   // [stage][m][k]
    __shared__ float Bs[2][TBK][BPAD];   // [stage][k][n]

    float acc[2][8][4];
#pragma unroll
    for (int i = 0; i < 2; i++)
#pragma unroll
        for (int j = 0; j < 8; j++)
#pragma unroll
            for (int q = 0; q < 4; q++) acc[i][j][q] = 0.f;

    const int row = lane >> 2;   // 0..7
    const int kc  = lane & 3;    // 0..3

    const int am0 = (tid * 2)     >> 2, ak0 = (tid * 2)     & 3;
    const int am1 = (tid * 2 + 1) >> 2, ak1 = (tid * 2 + 1) & 3;
    const int bk0 = (tid * 2)     >> 5, bn0c = (tid * 2)     & 31;
    const int bk1 = (tid * 2 + 1) >> 5, bn1c = (tid * 2 + 1) & 31;

    uint32_t asBase = (uint32_t)__cvta_generic_to_shared(&As[0][0][0]);
    uint32_t bsBase = (uint32_t)__cvta_generic_to_shared(&Bs[0][0][0]);
    const uint32_t asStage = TBM * APAD * 4;
    const uint32_t bsStage = TBK * BPAD * 4;

    const int nkt = K / TBK;

    // prologue: stage 0
    {
        cpasync16(asBase + (am0 * APAD + ak0 * 4) * 4,
                  A + (size_t)(m0 + am0) * K + ak0 * 4);
        cpasync16(asBase + (am1 * APAD + ak1 * 4) * 4,
                  A + (size_t)(m0 + am1) * K + ak1 * 4);
        cpasync16(bsBase + (bk0 * BPAD + bn0c * 4) * 4,
                  Bb + (size_t)bk0 * THW + n0 + bn0c * 4);
        cpasync16(bsBase + (bk1 * BPAD + bn1c * 4) * 4,
                  Bb + (size_t)bk1 * THW + n0 + bn1c * 4);
        asm volatile("cp.async.commit_group;\n");
    }

    for (int i = 0; i < nkt; i++) {
        const int s = i & 1;
        if (i + 1 < nkt) {
            const int kt = (i + 1) * TBK;
            const uint32_t so = (s ^ 1);
            cpasync16(asBase + so * asStage + (am0 * APAD + ak0 * 4) * 4,
                      A + (size_t)(m0 + am0) * K + kt + ak0 * 4);
            cpasync16(asBase + so * asStage + (am1 * APAD + ak1 * 4) * 4,
                      A + (size_t)(m0 + am1) * K + kt + ak1 * 4);
            cpasync16(bsBase + so * bsStage + (bk0 * BPAD + bn0c * 4) * 4,
                      Bb + (size_t)(kt + bk0) * THW + n0 + bn0c * 4);
            cpasync16(bsBase + so * bsStage + (bk1 * BPAD + bn1c * 4) * 4,
                      Bb + (size_t)(kt + bk1) * THW + n0 + bn1c * 4);
            asm volatile("cp.async.commit_group;\n");
            asm volatile("cp.async.wait_group 1;\n");
        } else {
            asm volatile("cp.async.wait_group 0;\n");
        }
        __syncthreads();

#pragma unroll
        for (int ks = 0; ks < 2; ks++) {
            const int kb = ks * 8;
            uint32_t af[2][4];
#pragma unroll
            for (int mt = 0; mt < 2; mt++) {
                int mr = wm * 32 + mt * 16 + row;
                af[mt][0] = f2tf32(As[s][mr    ][kb + kc    ]);
                af[mt][1] = f2tf32(As[s][mr + 8][kb + kc    ]);
                af[mt][2] = f2tf32(As[s][mr    ][kb + kc + 4]);
                af[mt][3] = f2tf32(As[s][mr + 8][kb + kc + 4]);
            }
            uint32_t bf[8][2];
#pragma unroll
            for (int nt = 0; nt < 8; nt++) {
                int nc = wn * 64 + nt * 8 + row;
                bf[nt][0] = f2tf32(Bs[s][kb + kc    ][nc]);
                bf[nt][1] = f2tf32(Bs[s][kb + kc + 4][nc]);
            }
#pragma unroll
            for (int mt = 0; mt < 2; mt++)
#pragma unroll
                for (int nt = 0; nt < 8; nt++) {
                    asm volatile(
                        "mma.sync.aligned.m16n8k8.row.col.f32.tf32.tf32.f32 "
                        "{%0,%1,%2,%3}, {%4,%5,%6,%7}, {%8,%9}, {%0,%1,%2,%3};"
                        : "+f"(acc[mt][nt][0]), "+f"(acc[mt][nt][1]),
                          "+f"(acc[mt][nt][2]), "+f"(acc[mt][nt][3])
                        : "r"(af[mt][0]), "r"(af[mt][1]),
                          "r"(af[mt][2]), "r"(af[mt][3]),
                          "r"(bf[nt][0]), "r"(bf[nt][1]));
                }
        }
        __syncthreads();
    }

    const int coln = 2 * (lane & 3);
#pragma unroll
    for (int mt = 0; mt < 2; mt++) {
#pragma unroll
        for (int half = 0; half < 2; half++) {
            int m = m0 + wm * 32 + mt * 16 + row + half * 8;
            float bi = bias[m];
            float sc = 1.f, sh = 0.f;
            if (mode == 1) {
                sc = gamma[m] * rsqrtf(bn_var[m] + BN_EPS);
                sh = beta[m] - bn_mean[m] * sc;
            }
#pragma unroll
            for (int nt = 0; nt < 8; nt++) {
                int n = n0 + wn * 64 + nt * 8 + coln;
                float v0 = acc[mt][nt][half * 2 + 0] + bi;
                float v1 = acc[mt][nt][half * 2 + 1] + bi;
                if (mode == 1) {
                    const float* xr = xres + (size_t)b * CC * THW + (size_t)m * THW + n;
                    v0 = v0 * sc + sh + xr[0];
                    v1 = v1 * sc + sh + xr[1];
                }
                *reinterpret_cast<float2*>(&Cb[(size_t)m * THW + n]) =
                    make_float2(v0, v1);
            }
        }
    }
}

// ---------------------------------------------------------------------------
// Pruned warp top-k (unchanged — known good)
// ---------------------------------------------------------------------------
template<int J>
__device__ __forceinline__ void shflStepRT(float* v, bool tm) {
#pragma unroll
    for (int r = 0; r < 32; r++) {
        float p  = __shfl_xor_sync(0xffffffffu, v[r], J);
        float mn = fminf(v[r], p), mx = fmaxf(v[r], p);
        v[r] = tm ? mx : mn;
    }
}
template<int J, int KR>
__device__ __forceinline__ void shflStepCT(float* v, bool loJ) {
#pragma unroll
    for (int r = 0; r < 32; r++) {
        const bool tm = ((r & KR) == 0) ? true : false;
        float p  = __shfl_xor_sync(0xffffffffu, v[r], J);
        float mn = fminf(v[r], p), mx = fmaxf(v[r], p);
        v[r] = (tm ? loJ : !loJ) ? mx : mn;
    }
}
template<int JR, int KR>
__device__ __forceinline__ void regStep(float* v) {
#pragma unroll
    for (int r = 0; r < 32; r++) if (!(r & JR)) {
        float a = v[r], b = v[r | JR];
        if ((r & KR) == 0) { v[r] = fmaxf(a, b); v[r | JR] = fminf(a, b); }
        else               { v[r] = fminf(a, b); v[r | JR] = fmaxf(a, b); }
    }
}
template<int KR>
__device__ __forceinline__ void shflSweepCT(float* v, bool lo16, bool lo8,
                                            bool lo4, bool lo2, bool lo1) {
    shflStepCT<16, KR>(v, lo16);
    shflStepCT<8,  KR>(v, lo8);
    shflStepCT<4,  KR>(v, lo4);
    shflStepCT<2,  KR>(v, lo2);
    shflStepCT<1,  KR>(v, lo1);
}
template<int JR>
__device__ __forceinline__ void mergeStepDual(float* v) {
#pragma unroll
    for (int q = 0; q < 8; q++) if (!(q & JR)) {
        { float a = v[q], b = v[q | JR];
          v[q] = fmaxf(a, b); v[q | JR] = fminf(a, b); }
        { float a = v[16 + q], b = v[16 + (q | JR)];
          v[16 + q] = fminf(a, b); v[16 + (q | JR)] = fmaxf(a, b); }
    }
}
template<int J>
__device__ __forceinline__ void shflMergeDual(float* v, bool loJ) {
#pragma unroll
    for (int q = 0; q < 8; q++) {
        { float p = __shfl_xor_sync(0xffffffffu, v[q], J);
          float mn = fminf(v[q], p), mx = fmaxf(v[q], p);
          v[q] = loJ ? mx : mn; }
        { float p = __shfl_xor_sync(0xffffffffu, v[16 + q], J);
          float mn = fminf(v[16 + q], p), mx = fmaxf(v[16 + q], p);
          v[16 + q] = loJ ? mn : mx; }
    }
}
template<int JR>
__device__ __forceinline__ void mergeStepFinal(float* v) {
#pragma unroll
    for (int q = 0; q < 8; q++) if (!(q & JR)) {
        float a = v[q], b = v[q | JR];
        v[q] = fmaxf(a, b); v[q | JR] = fminf(a, b);
    }
}
template<int J>
__device__ __forceinline__ void shflFinal(float* v, bool loJ) {
#pragma unroll
    for (int q = 0; q < 8; q++) {
        float p  = __shfl_xor_sync(0xffffffffu, v[q], J);
        float mn = fminf(v[q], p), mx = fmaxf(v[q], p);
        v[q] = loJ ? mx : mn;
    }
}

__global__ __launch_bounds__(256) void topk_warp_kernel(
    const float* __restrict__ srcQ, float* __restrict__ dstQ,
    const float* __restrict__ srcK, float* __restrict__ dstK, int nrows)
{
    const int lane = threadIdx.x & 31;
    const int row  = blockIdx.x * (blockDim.x >> 5) + (threadIdx.x >> 5);
    if (row >= nrows) return;

    const float* src = blockIdx.y ? srcK : srcQ;
    float*       dst = blockIdx.y ? dstK : dstQ;

    const float* rp = src + (size_t)row * HWD;
    float v[32];
#pragma unroll
    for (int r = 0; r < 24; r++) v[r] = rp[r * 32 + lane];
    v[24] = (lane < 16) ? rp[24 * 32 + lane] : -CUDART_INF_F;
#pragma unroll
    for (int r = 25; r < 32; r++) v[r] = -CUDART_INF_F;

    const bool lo1  = (lane & 1)  == 0;
    const bool lo2  = (lane & 2)  == 0;
    const bool lo4  = (lane & 4)  == 0;
    const bool lo8  = (lane & 8)  == 0;
    const bool lo16 = (lane & 16) == 0;

    shflStepRT<1>(v, lo2 == lo1);
    shflStepRT<2>(v, lo4 == lo2);
    shflStepRT<1>(v, lo4 == lo1);
    shflStepRT<4>(v, lo8 == lo4);
    shflStepRT<2>(v, lo8 == lo2);
    shflStepRT<1>(v, lo8 == lo1);
    shflStepRT<8>(v, lo16 == lo8);
    shflStepRT<4>(v, lo16 == lo4);
    shflStepRT<2>(v, lo16 == lo2);
    shflStepRT<1>(v, lo16 == lo1);

    shflSweepCT<1>(v, lo16, lo8, lo4, lo2, lo1);
    regStep<1, 2>(v);
    shflSweepCT<2>(v, lo16, lo8, lo4, lo2, lo1);
    regStep<2, 4>(v); regStep<1, 4>(v);
    shflSweepCT<4>(v, lo16, lo8, lo4, lo2, lo1);
    regStep<4, 8>(v); regStep<2, 8>(v); regStep<1, 8>(v);
    shflSweepCT<8>(v, lo16, lo8, lo4, lo2, lo1);

#pragma unroll
    for (int q = 0; q < 8; q++) {
        { float a = v[q],      b = v[q + 8];
          v[q]      = fmaxf(a, b); v[q + 8]  = fminf(a, b); }
        { float a = v[16 + q], b = v[24 + q];
          v[16 + q] = fmaxf(a, b); v[24 + q] = fminf(a, b); }
    }
    mergeStepDual<4>(v); mergeStepDual<2>(v); mergeStepDual<1>(v);
    shflMergeDual<16>(v, lo16); shflMergeDual<8>(v, lo8);
    shflMergeDual<4>(v, lo4);   shflMergeDual<2>(v, lo2);
    shflMergeDual<1>(v, lo1);
#pragma unroll
    for (int q = 0; q < 8; q++) v[q] = fmaxf(v[q], v[16 + q]);
    mergeStepFinal<4>(v); mergeStepFinal<2>(v); mergeStepFinal<1>(v);
    shflFinal<16>(v, lo16); shflFinal<8>(v, lo8);
    shflFinal<4>(v, lo4);   shflFinal<2>(v, lo2);
    shflFinal<1>(v, lo1);

    float* dp = dst + (size_t)row * KTOP;
#pragma unroll
    for (int r = 0; r < 6; r++) dp[r * 32 + lane] = v[r];
    if (lane < 4) dp[6 * 32 + lane] = v[6];
}

// ---------------------------------------------------------------------------
// Attention (unchanged)
// ---------------------------------------------------------------------------
__global__ __launch_bounds__(256) void attn_kernel(
    const float* __restrict__ Qt, const float* __restrict__ Kt,
    const float* __restrict__ V, float* __restrict__ Y)
{
    __shared__ float sQ[TT * KTOP];
    __shared__ float sK[TT * KTOP];
    __shared__ float sA[TT * TT];

    const int n   = blockIdx.x;
    const int tid = threadIdx.x;

    const float* qb = Qt + (long)n * TT * KTOP;
    const float* kb = Kt + (long)n * TT * KTOP;
    for (int i = tid; i < TT * KTOP; i += 256) { sQ[i] = qb[i]; sK[i] = kb[i]; }
    __syncthreads();

    {
        int t = tid >> 4, s = tid & 15;
        const float4* q4 = reinterpret_cast<const float4*>(sQ + t * KTOP);
        const float4* k4 = reinterpret_cast<const float4*>(sK + s * KTOP);
        float acc = 0.f;
#pragma unroll 7
        for (int j = 0; j < KTOP / 4; j++) {
            float4 a = q4[j], b = k4[j];
            acc = fmaf(a.x, b.x, acc);
            acc = fmaf(a.y, b.y, acc);
            acc = fmaf(a.z, b.z, acc);
            acc = fmaf(a.w, b.w, acc);
        }
        sA[t * 16 + s] = acc;
    }
    __syncthreads();

    if (tid < TT) {
        int t = tid;
        float mx = -CUDART_INF_F;
#pragma unroll
        for (int s = 0; s < 16; s++) mx = fmaxf(mx, sA[t * 16 + s]);
        float sum = 0.f;
        float e[16];
#pragma unroll
        for (int s = 0; s < 16; s++) { e[s] = __expf(sA[t * 16 + s] - mx); sum += e[s]; }
        float inv = 1.f / sum;
#pragma unroll
        for (int s = 0; s < 16; s++) sA[t * 16 + s] = e[s] * inv;
    }
    __syncthreads();

    const float* vb = V + (long)n * THW;
    float* yb = Y + (long)n * THW;
    for (int p = tid; p < HWD; p += 256) {
        float v[TT];
#pragma unroll
        for (int s = 0; s < TT; s++) v[s] = vb[s * HWD + p];
#pragma unroll
        for (int t = 0; t < TT; t++) {
            float acc = 0.f;
#pragma unroll
            for (int s = 0; s < TT; s++) acc = fmaf(sA[t * 16 + s], v[s], acc);
            yb[t * HWD + p] = acc;
        }
    }
}

// ---------------------------------------------------------------------------
extern "C" void kernel_launch(void* const* d_in, const int* in_sizes, int n_in,
                              void* d_out, int out_size)
{
    const float* x      = (const float*)d_in[0];
    const float* Wq     = (const float*)d_in[1];
    const float* bq     = (const float*)d_in[2];
    const float* Wk     = (const float*)d_in[3];
    const float* bk     = (const float*)d_in[4];
    const float* Wv     = (const float*)d_in[5];
    const float* bv     = (const float*)d_in[6];
    const float* Wr     = (const float*)d_in[7];
    const float* br     = (const float*)d_in[8];
    const float* gamma  = (const float*)d_in[9];
    const float* beta   = (const float*)d_in[10];
    const float* bnmean = (const float*)d_in[11];
    const float* bnvar  = (const float*)d_in[12];
    float* out = (float*)d_out;

    float *Qp, *Kp, *Vp, *Qtp, *Ktp, *Yp;
    cudaGetSymbolAddress((void**)&Qp,  g_Q);
    cudaGetSymbolAddress((void**)&Kp,  g_K);
    cudaGetSymbolAddress((void**)&Vp,  g_V);
    cudaGetSymbolAddress((void**)&Qtp, g_Qt);
    cudaGetSymbolAddress((void**)&Ktp, g_Kt);
    cudaGetSymbolAddress((void**)&Yp,  g_Y);

    // Fused QKV: grid.x selects (W, bias, out)
    dim3 gQKV(3, THW / TBN, BB);             // (3, 98, 8)
    gemm_tf32_pipe_kernel<<<gQKV, 256>>>(
        Wq, Wk, Wv, x, Qp, Kp, Vp, bq, bk, bv,
        nullptr, nullptr, nullptr, nullptr, nullptr, CR, CC, 0);

    const int nrows = NROW * TT;             // 16384
    const int wpb = 8;
    dim3 gTK((nrows + wpb - 1) / wpb, 2);
    topk_warp_kernel<<<gTK, 32 * wpb>>>(Qp, Qtp, Kp, Ktp, nrows);

    attn_kernel<<<NROW, 256>>>(Qtp, Ktp, Vp, Yp);

    // Reconstruct: grid.x = m-tile
    dim3 gRec(CC / TBM, THW / TBN, BB);      // (2, 98, 8)
    gemm_tf32_pipe_kernel<<<gRec, 256>>>(
        Wr, nullptr, nullptr, Yp, out, nullptr, nullptr, br, nullptr, nullptr,
        gamma, beta, bnmean, bnvar, x, CC, CR, 1);
}

// round 9
// speedup vs baseline: 1.5074x; 1.5074x over previous
#include <cuda_runtime.h>
#include <math_constants.h>
#include <cstdint>

// Problem constants
#define BB   8
#define CC   256
#define CR   128
#define TT   16
#define HWD  784            // 28*28
#define THW  12544          // 16*784
#define KTOP 196            // 784/4
#define NROW 1024           // B*CR
#define BN_EPS 1e-5f

// Scratch buffers
__device__ float g_Q [BB * CR * THW];
__device__ float g_K [BB * CR * THW];
__device__ float g_V [BB * CR * THW];
__device__ float g_Qt[NROW * TT * KTOP];
__device__ float g_Kt[NROW * TT * KTOP];
__device__ float g_Y [BB * CR * THW];

__device__ __forceinline__ uint32_t f2tf32(float x) {
    uint32_t u;
    asm("cvt.rna.tf32.f32 %0, %1;" : "=r"(u) : "f"(x));
    return u;
}
__device__ __forceinline__ void cpasync16(uint32_t daddr, const void* src) {
    asm volatile("cp.async.ca.shared.global [%0], [%1], 16;\n"
                 :: "r"(daddr), "l"(src));
}

// ---------------------------------------------------------------------------
// Pipelined tf32 GEMM, 2-stage cp.async, 512 threads (16 warps, 4Mx4N),
// warp tile 32x32 -> acc 32 regs/thread, no spills, 4 warps/SMSP.
// ---------------------------------------------------------------------------
#define TBM 128
#define TBN 128
#define TBK 16
#define APAD 20
#define BPAD 136

__global__ __launch_bounds__(512) void gemm_tf32_pipe_kernel(
    const float* __restrict__ A0, const float* __restrict__ A1,
    const float* __restrict__ A2,
    const float* __restrict__ Bmat,
    float* __restrict__ C0, float* __restrict__ C1, float* __restrict__ C2,
    const float* __restrict__ bias0, const float* __restrict__ bias1,
    const float* __restrict__ bias2,
    const float* __restrict__ gamma,
    const float* __restrict__ beta,
    const float* __restrict__ bn_mean,
    const float* __restrict__ bn_var,
    const float* __restrict__ xres,
    int M, int K, int mode)
{
    const int b    = blockIdx.z;
    const int bx   = blockIdx.x;
    const int n0   = blockIdx.y * TBN;
    const int tid  = threadIdx.x;
    const int lane = tid & 31;
    const int wid  = tid >> 5;          // 0..15
    const int wm   = wid >> 2;          // 0..3 (M)
    const int wn   = wid & 3;           // 0..3 (N)

    const float* A;
    const float* bias;
    float* C;
    int m0;
    if (mode == 0) {
        A    = (bx == 0) ? A0 : (bx == 1) ? A1 : A2;
        bias = (bx == 0) ? bias0 : (bx == 1) ? bias1 : bias2;
        C    = (bx == 0) ? C0 : (bx == 1) ? C1 : C2;
        m0   = 0;
    } else {
        A = A0; bias = bias0; C = C0;
        m0 = bx * TBM;
    }

    const float* Bb = Bmat + (size_t)b * K * THW;
    float*       Cb = C    + (size_t)b * M * THW;

    __shared__ float As[2][TBM][APAD];   // [stage][m][k]
    __shared__ float Bs[2][TBK][BPAD];   // [stage][k][n]

    float acc[2][4][4];
#pragma unroll
    for (int i = 0; i < 2; i++)
#pragma unroll
        for (int j = 0; j < 4; j++)
#pragma unroll
            for (int q = 0; q < 4; q++) acc[i][j][q] = 0.f;

    const int row = lane >> 2;   // 0..7
    const int kc  = lane & 3;    // 0..3

    // cp.async: 512 threads, 1 chunk each per tile
    const int am = tid >> 2, ak = tid & 3;    // A: 128 rows x 4 chunks
    const int bk = tid >> 5, bn = tid & 31;   // B: 16 rows x 32 chunks

    uint32_t asBase = (uint32_t)__cvta_generic_to_shared(&As[0][0][0]);
    uint32_t bsBase = (uint32_t)__cvta_generic_to_shared(&Bs[0][0][0]);
    const uint32_t asStage = TBM * APAD * 4;
    const uint32_t bsStage = TBK * BPAD * 4;

    const int nkt = K / TBK;

    // prologue: stage 0
    cpasync16(asBase + (am * APAD + ak * 4) * 4,
              A + (size_t)(m0 + am) * K + ak * 4);
    cpasync16(bsBase + (bk * BPAD + bn * 4) * 4,
              Bb + (size_t)bk * THW + n0 + bn * 4);
    asm volatile("cp.async.commit_group;\n");

    for (int i = 0; i < nkt; i++) {
        const int s = i & 1;
        if (i + 1 < nkt) {
            const int kt = (i + 1) * TBK;
            const uint32_t so = (s ^ 1);
            cpasync16(asBase + so * asStage + (am * APAD + ak * 4) * 4,
                      A + (size_t)(m0 + am) * K + kt + ak * 4);
            cpasync16(bsBase + so * bsStage + (bk * BPAD + bn * 4) * 4,
                      Bb + (size_t)(kt + bk) * THW + n0 + bn * 4);
            asm volatile("cp.async.commit_group;\n");
            asm volatile("cp.async.wait_group 1;\n");
        } else {
            asm volatile("cp.async.wait_group 0;\n");
        }
        __syncthreads();

#pragma unroll
        for (int ks = 0; ks < 2; ks++) {
            const int kb = ks * 8;
            uint32_t af[2][4];
#pragma unroll
            for (int mt = 0; mt < 2; mt++) {
                int mr = wm * 32 + mt * 16 + row;
                af[mt][0] = f2tf32(As[s][mr    ][kb + kc    ]);
                af[mt][1] = f2tf32(As[s][mr + 8][kb + kc    ]);
                af[mt][2] = f2tf32(As[s][mr    ][kb + kc + 4]);
                af[mt][3] = f2tf32(As[s][mr + 8][kb + kc + 4]);
            }
            uint32_t bf[4][2];
#pragma unroll
            for (int nt = 0; nt < 4; nt++) {
                int nc = wn * 32 + nt * 8 + row;
                bf[nt][0] = f2tf32(Bs[s][kb + kc    ][nc]);
                bf[nt][1] = f2tf32(Bs[s][kb + kc + 4][nc]);
            }
#pragma unroll
            for (int mt = 0; mt < 2; mt++)
#pragma unroll
                for (int nt = 0; nt < 4; nt++) {
                    asm volatile(
                        "mma.sync.aligned.m16n8k8.row.col.f32.tf32.tf32.f32 "
                        "{%0,%1,%2,%3}, {%4,%5,%6,%7}, {%8,%9}, {%0,%1,%2,%3};"
                        : "+f"(acc[mt][nt][0]), "+f"(acc[mt][nt][1]),
                          "+f"(acc[mt][nt][2]), "+f"(acc[mt][nt][3])
                        : "r"(af[mt][0]), "r"(af[mt][1]),
                          "r"(af[mt][2]), "r"(af[mt][3]),
                          "r"(bf[nt][0]), "r"(bf[nt][1]));
                }
        }
        __syncthreads();
    }

    // Epilogue. c0:(row,col) c1:(row,col+1) c2:(row+8,col) c3:(row+8,col+1)
    const int coln = 2 * (lane & 3);
#pragma unroll
    for (int mt = 0; mt < 2; mt++) {
#pragma unroll
        for (int half = 0; half < 2; half++) {
            int m = m0 + wm * 32 + mt * 16 + row + half * 8;
            float bi = bias[m];
            float sc = 1.f, sh = 0.f;
            if (mode == 1) {
                sc = gamma[m] * rsqrtf(bn_var[m] + BN_EPS);
                sh = beta[m] - bn_mean[m] * sc;
            }
#pragma unroll
            for (int nt = 0; nt < 4; nt++) {
                int n = n0 + wn * 32 + nt * 8 + coln;
                float v0 = acc[mt][nt][half * 2 + 0] + bi;
                float v1 = acc[mt][nt][half * 2 + 1] + bi;
                if (mode == 1) {
                    const float* xr = xres + (size_t)b * CC * THW + (size_t)m * THW + n;
                    v0 = v0 * sc + sh + xr[0];
                    v1 = v1 * sc + sh + xr[1];
                }
                *reinterpret_cast<float2*>(&Cb[(size_t)m * THW + n]) =
                    make_float2(v0, v1);
            }
        }
    }
}

// ---------------------------------------------------------------------------
// Pruned warp top-k (unchanged — known good)
// ---------------------------------------------------------------------------
template<int J>
__device__ __forceinline__ void shflStepRT(float* v, bool tm) {
#pragma unroll
    for (int r = 0; r < 32; r++) {
        float p  = __shfl_xor_sync(0xffffffffu, v[r], J);
        float mn = fminf(v[r], p), mx = fmaxf(v[r], p);
        v[r] = tm ? mx : mn;
    }
}
template<int J, int KR>
__device__ __forceinline__ void shflStepCT(float* v, bool loJ) {
#pragma unroll
    for (int r = 0; r < 32; r++) {
        const bool tm = ((r & KR) == 0) ? true : false;
        float p  = __shfl_xor_sync(0xffffffffu, v[r], J);
        float mn = fminf(v[r], p), mx = fmaxf(v[r], p);
        v[r] = (tm ? loJ : !loJ) ? mx : mn;
    }
}
template<int JR, int KR>
__device__ __forceinline__ void regStep(float* v) {
#pragma unroll
    for (int r = 0; r < 32; r++) if (!(r & JR)) {
        float a = v[r], b = v[r | JR];
        if ((r & KR) == 0) { v[r] = fmaxf(a, b); v[r | JR] = fminf(a, b); }
        else               { v[r] = fminf(a, b); v[r | JR] = fmaxf(a, b); }
    }
}
template<int KR>
__device__ __forceinline__ void shflSweepCT(float* v, bool lo16, bool lo8,
                                            bool lo4, bool lo2, bool lo1) {
    shflStepCT<16, KR>(v, lo16);
    shflStepCT<8,  KR>(v, lo8);
    shflStepCT<4,  KR>(v, lo4);
    shflStepCT<2,  KR>(v, lo2);
    shflStepCT<1,  KR>(v, lo1);
}
template<int JR>
__device__ __forceinline__ void mergeStepDual(float* v) {
#pragma unroll
    for (int q = 0; q < 8; q++) if (!(q & JR)) {
        { float a = v[q], b = v[q | JR];
          v[q] = fmaxf(a, b); v[q | JR] = fminf(a, b); }
        { float a = v[16 + q], b = v[16 + (q | JR)];
          v[16 + q] = fminf(a, b); v[16 + (q | JR)] = fmaxf(a, b); }
    }
}
template<int J>
__device__ __forceinline__ void shflMergeDual(float* v, bool loJ) {
#pragma unroll
    for (int q = 0; q < 8; q++) {
        { float p = __shfl_xor_sync(0xffffffffu, v[q], J);
          float mn = fminf(v[q], p), mx = fmaxf(v[q], p);
          v[q] = loJ ? mx : mn; }
        { float p = __shfl_xor_sync(0xffffffffu, v[16 + q], J);
          float mn = fminf(v[16 + q], p), mx = fmaxf(v[16 + q], p);
          v[16 + q] = loJ ? mn : mx; }
    }
}
template<int JR>
__device__ __forceinline__ void mergeStepFinal(float* v) {
#pragma unroll
    for (int q = 0; q < 8; q++) if (!(q & JR)) {
        float a = v[q], b = v[q | JR];
        v[q] = fmaxf(a, b); v[q | JR] = fminf(a, b);
    }
}
template<int J>
__device__ __forceinline__ void shflFinal(float* v, bool loJ) {
#pragma unroll
    for (int q = 0; q < 8; q++) {
        float p  = __shfl_xor_sync(0xffffffffu, v[q], J);
        float mn = fminf(v[q], p), mx = fmaxf(v[q], p);
        v[q] = loJ ? mx : mn;
    }
}

__global__ __launch_bounds__(256) void topk_warp_kernel(
    const float* __restrict__ srcQ, float* __restrict__ dstQ,
    const float* __restrict__ srcK, float* __restrict__ dstK, int nrows)
{
    const int lane = threadIdx.x & 31;
    const int row  = blockIdx.x * (blockDim.x >> 5) + (threadIdx.x >> 5);
    if (row >= nrows) return;

    const float* src = blockIdx.y ? srcK : srcQ;
    float*       dst = blockIdx.y ? dstK : dstQ;

    const float* rp = src + (size_t)row * HWD;
    float v[32];
#pragma unroll
    for (int r = 0; r < 24; r++) v[r] = rp[r * 32 + lane];
    v[24] = (lane < 16) ? rp[24 * 32 + lane] : -CUDART_INF_F;
#pragma unroll
    for (int r = 25; r < 32; r++) v[r] = -CUDART_INF_F;

    const bool lo1  = (lane & 1)  == 0;
    const bool lo2  = (lane & 2)  == 0;
    const bool lo4  = (lane & 4)  == 0;
    const bool lo8  = (lane & 8)  == 0;
    const bool lo16 = (lane & 16) == 0;

    shflStepRT<1>(v, lo2 == lo1);
    shflStepRT<2>(v, lo4 == lo2);
    shflStepRT<1>(v, lo4 == lo1);
    shflStepRT<4>(v, lo8 == lo4);
    shflStepRT<2>(v, lo8 == lo2);
    shflStepRT<1>(v, lo8 == lo1);
    shflStepRT<8>(v, lo16 == lo8);
    shflStepRT<4>(v, lo16 == lo4);
    shflStepRT<2>(v, lo16 == lo2);
    shflStepRT<1>(v, lo16 == lo1);

    shflSweepCT<1>(v, lo16, lo8, lo4, lo2, lo1);
    regStep<1, 2>(v);
    shflSweepCT<2>(v, lo16, lo8, lo4, lo2, lo1);
    regStep<2, 4>(v); regStep<1, 4>(v);
    shflSweepCT<4>(v, lo16, lo8, lo4, lo2, lo1);
    regStep<4, 8>(v); regStep<2, 8>(v); regStep<1, 8>(v);
    shflSweepCT<8>(v, lo16, lo8, lo4, lo2, lo1);

#pragma unroll
    for (int q = 0; q < 8; q++) {
        { float a = v[q],      b = v[q + 8];
          v[q]      = fmaxf(a, b); v[q + 8]  = fminf(a, b); }
        { float a = v[16 + q], b = v[24 + q];
          v[16 + q] = fmaxf(a, b); v[24 + q] = fminf(a, b); }
    }
    mergeStepDual<4>(v); mergeStepDual<2>(v); mergeStepDual<1>(v);
    shflMergeDual<16>(v, lo16); shflMergeDual<8>(v, lo8);
    shflMergeDual<4>(v, lo4);   shflMergeDual<2>(v, lo2);
    shflMergeDual<1>(v, lo1);
#pragma unroll
    for (int q = 0; q < 8; q++) v[q] = fmaxf(v[q], v[16 + q]);
    mergeStepFinal<4>(v); mergeStepFinal<2>(v); mergeStepFinal<1>(v);
    shflFinal<16>(v, lo16); shflFinal<8>(v, lo8);
    shflFinal<4>(v, lo4);   shflFinal<2>(v, lo2);
    shflFinal<1>(v, lo1);

    float* dp = dst + (size_t)row * KTOP;
#pragma unroll
    for (int r = 0; r < 6; r++) dp[r * 32 + lane] = v[r];
    if (lane < 4) dp[6 * 32 + lane] = v[6];
}

// ---------------------------------------------------------------------------
// Attention (unchanged)
// ---------------------------------------------------------------------------
__global__ __launch_bounds__(256) void attn_kernel(
    const float* __restrict__ Qt, const float* __restrict__ Kt,
    const float* __restrict__ V, float* __restrict__ Y)
{
    __shared__ float sQ[TT * KTOP];
    __shared__ float sK[TT * KTOP];
    __shared__ float sA[TT * TT];

    const int n   = blockIdx.x;
    const int tid = threadIdx.x;

    const float* qb = Qt + (long)n * TT * KTOP;
    const float* kb = Kt + (long)n * TT * KTOP;
    for (int i = tid; i < TT * KTOP; i += 256) { sQ[i] = qb[i]; sK[i] = kb[i]; }
    __syncthreads();

    {
        int t = tid >> 4, s = tid & 15;
        const float4* q4 = reinterpret_cast<const float4*>(sQ + t * KTOP);
        const float4* k4 = reinterpret_cast<const float4*>(sK + s * KTOP);
        float acc = 0.f;
#pragma unroll 7
        for (int j = 0; j < KTOP / 4; j++) {
            float4 a = q4[j], b = k4[j];
            acc = fmaf(a.x, b.x, acc);
            acc = fmaf(a.y, b.y, acc);
            acc = fmaf(a.z, b.z, acc);
            acc = fmaf(a.w, b.w, acc);
        }
        sA[t * 16 + s] = acc;
    }
    __syncthreads();

    if (tid < TT) {
        int t = tid;
        float mx = -CUDART_INF_F;
#pragma unroll
        for (int s = 0; s < 16; s++) mx = fmaxf(mx, sA[t * 16 + s]);
        float sum = 0.f;
        float e[16];
#pragma unroll
        for (int s = 0; s < 16; s++) { e[s] = __expf(sA[t * 16 + s] - mx); sum += e[s]; }
        float inv = 1.f / sum;
#pragma unroll
        for (int s = 0; s < 16; s++) sA[t * 16 + s] = e[s] * inv;
    }
    __syncthreads();

    const float* vb = V + (long)n * THW;
    float* yb = Y + (long)n * THW;
    for (int p = tid; p < HWD; p += 256) {
        float v[TT];
#pragma unroll
        for (int s = 0; s < TT; s++) v[s] = vb[s * HWD + p];
#pragma unroll
        for (int t = 0; t < TT; t++) {
            float acc = 0.f;
#pragma unroll
            for (int s = 0; s < TT; s++) acc = fmaf(sA[t * 16 + s], v[s], acc);
            yb[t * HWD + p] = acc;
        }
    }
}

// ---------------------------------------------------------------------------
extern "C" void kernel_launch(void* const* d_in, const int* in_sizes, int n_in,
                              void* d_out, int out_size)
{
    const float* x      = (const float*)d_in[0];
    const float* Wq     = (const float*)d_in[1];
    const float* bq     = (const float*)d_in[2];
    const float* Wk     = (const float*)d_in[3];
    const float* bk     = (const float*)d_in[4];
    const float* Wv     = (const float*)d_in[5];
    const float* bv     = (const float*)d_in[6];
    const float* Wr     = (const float*)d_in[7];
    const float* br     = (const float*)d_in[8];
    const float* gamma  = (const float*)d_in[9];
    const float* beta   = (const float*)d_in[10];
    const float* bnmean = (const float*)d_in[11];
    const float* bnvar  = (const float*)d_in[12];
    float* out = (float*)d_out;

    float *Qp, *Kp, *Vp, *Qtp, *Ktp, *Yp;
    cudaGetSymbolAddress((void**)&Qp,  g_Q);
    cudaGetSymbolAddress((void**)&Kp,  g_K);
    cudaGetSymbolAddress((void**)&Vp,  g_V);
    cudaGetSymbolAddress((void**)&Qtp, g_Qt);
    cudaGetSymbolAddress((void**)&Ktp, g_Kt);
    cudaGetSymbolAddress((void**)&Yp,  g_Y);

    // Fused QKV: grid.x selects (W, bias, out)
    dim3 gQKV(3, THW / TBN, BB);             // (3, 98, 8)
    gemm_tf32_pipe_kernel<<<gQKV, 512>>>(
        Wq, Wk, Wv, x, Qp, Kp, Vp, bq, bk, bv,
        nullptr, nullptr, nullptr, nullptr, nullptr, CR, CC, 0);

    const int nrows = NROW * TT;             // 16384
    const int wpb = 8;
    dim3 gTK((nrows + wpb - 1) / wpb, 2);
    topk_warp_kernel<<<gTK, 32 * wpb>>>(Qp, Qtp, Kp, Ktp, nrows);

    attn_kernel<<<NROW, 256>>>(Qtp, Ktp, Vp, Yp);

    // Reconstruct: grid.x = m-tile
    dim3 gRec(CC / TBM, THW / TBN, BB);      // (2, 98, 8)
    gemm_tf32_pipe_kernel<<<gRec, 512>>>(
        Wr, nullptr, nullptr, Yp, out, nullptr, nullptr, br, nullptr, nullptr,
        gamma, beta, bnmean, bnvar, x, CC, CR, 1);
}